// round 14
// baseline (speedup 1.0000x reference)
#include <cuda_runtime.h>
#include <cuda_bf16.h>
#include <cuda_fp16.h>
#include <math.h>
#include <stdint.h>

#define E_NUM   240000
#define N_NODES 20000
#define C       128
#define NGAUSS  600
#define ZMAX    100
#define NT      5504
#define TBL_H   0.00125f

#define DELTA_OFF 0.0100166944908180f
#define COEFF     (-1245.8368055555557f)

// ---------------- scratch ----------------
__device__ float  g_tbl[NT * C];
__device__ float4 g_w4[E_NUM];
__device__ int    g_i0[E_NUM];
__device__ uint32_t g_z[E_NUM];          // packed (zs | zt<<16)
__device__ float4 g_d1[E_NUM];
__device__ float  g_embU[2 * ZMAX * C];
__device__ uint2  g_w2h[4096];           // W2 fp16 HI only per (k*16+nt)*32+lane (32KB)
__device__ uint2  g_w3h[2][4096];        // W3 fp16 HI only, [half], n-permuted (64KB)

// smem: A1 hi 32KB, A1 lo 32KB (128 rows x 256B per term). Weights live in L1.
#define RA_HI 0
#define RA_LO 32768
#define SMEM_BYTES 65536

// swizzled row-major 16-bit tile offset: row r (0..127), 16B granule g (0..15)
__device__ __forceinline__ uint32_t swa(int r, int g) {
    return (uint32_t)(r * 256 + (((g) ^ (r & 7)) << 4));
}

// ---------------- PTX helpers ----------------
__device__ __forceinline__ void redv4(float* p, float a, float b, float c, float d) {
    asm volatile("red.global.add.v4.f32 [%0], {%1,%2,%3,%4};"
                 :: "l"(p), "f"(a), "f"(b), "f"(c), "f"(d) : "memory");
}
__device__ __forceinline__ void ldsm4(uint32_t& r0, uint32_t& r1, uint32_t& r2, uint32_t& r3,
                                      uint32_t addr) {
    asm volatile("ldmatrix.sync.aligned.m8n8.x4.shared.b16 {%0,%1,%2,%3}, [%4];"
                 : "=r"(r0), "=r"(r1), "=r"(r2), "=r"(r3) : "r"(addr));
}
__device__ __forceinline__ void mma16816h(float* c, uint32_t a0, uint32_t a1, uint32_t a2,
                                          uint32_t a3, uint32_t b0, uint32_t b1) {
    asm volatile("mma.sync.aligned.m16n8k16.row.col.f32.f16.f16.f32 "
                 "{%0,%1,%2,%3}, {%4,%5,%6,%7}, {%8,%9}, {%0,%1,%2,%3};"
                 : "+f"(c[0]), "+f"(c[1]), "+f"(c[2]), "+f"(c[3])
                 : "r"(a0), "r"(a1), "r"(a2), "r"(a3), "r"(b0), "r"(b1));
}
__device__ __forceinline__ uint32_t pack_f16(__half lo, __half hi) {
    return (uint32_t)__half_as_ushort(lo) | ((uint32_t)__half_as_ushort(hi) << 16);
}
__device__ __forceinline__ void split_f16(float v, __half& h, __half& l) {
    h = __float2half_rn(v);
    l = __float2half_rn(v - __half2float(h));
}

// ---------------- K1: F table ----------------
__global__ void k_table(const float* __restrict__ W1) {
    int row = blockIdx.x;
    int c   = threadIdx.x;
    float x = (row - 4) * TBL_H;
    int gc = (int)rintf(x / DELTA_OFF);
    int g0 = max(gc - 24, 0);
    int g1 = min(gc + 24, NGAUSS - 1);
    __shared__ float sw[64];
    int nw = g1 - g0 + 1;
    if (c < nw) {
        float o = (g0 + c) * DELTA_OFF;
        float dd = x - o;
        sw[c] = __expf(COEFF * dd * dd);
    }
    __syncthreads();
    float acc = 0.f;
    for (int j = 0; j < nw; j++)
        acc += sw[j] * W1[(g0 + j) * C + c];
    g_tbl[row * C + c] = acc;
}

// ---------------- K2: merged embW-fold + weight prepack ----------------
__global__ void k_prep2(const float* __restrict__ srce, const float* __restrict__ tgte,
                        const float* __restrict__ W1,
                        const float* __restrict__ W2, const float* __restrict__ W3) {
    if (blockIdx.x < ZMAX) {
        int z = blockIdx.x;
        int w = threadIdx.x >> 7;
        int c = threadIdx.x & 127;
        const float* emb = w ? tgte : srce;
        const float* Wb  = W1 + (NGAUSS + w * C) * C;
        __shared__ float se[2][C];
        se[w][c] = emb[z * C + c];
        __syncthreads();
        float acc = 0.f;
        #pragma unroll 8
        for (int k = 0; k < C; k++)
            acc = fmaf(se[w][k], Wb[k * C + c], acc);
        g_embU[(w * ZMAX + z) * C + c] = acc;
        return;
    }
    int idx = (blockIdx.x - ZMAX) * 256 + threadIdx.x;
    if (idx >= 12288) return;
    int lane = idx & 31;
    int nt   = (idx >> 5) & 15;
    int k    = (idx >> 9) & 7;
    int m    = idx >> 12;            // 0: W2, 1: W3 half0, 2: W3 half1
    int tig = lane & 3, gid = lane >> 2;
    int kg = k * 16 + tig * 2;
    float v0, v1, v2, v3;
    if (m == 0) {
        int n = nt * 8 + gid;
        v0 = W2[kg * C + n];       v1 = W2[(kg + 1) * C + n];
        v2 = W2[(kg + 8) * C + n]; v3 = W2[(kg + 9) * C + n];
        g_w2h[(k * 16 + nt) * 32 + lane] =
            make_uint2(pack_f16(__float2half_rn(v0), __float2half_rn(v1)),
                       pack_f16(__float2half_rn(v2), __float2half_rn(v3)));
    } else {
        // permuted: logical col L(nt=2q+p, j=gid) = q*16 + (j>>1)*4 + p*2 + (j&1)
        int q = nt >> 1, p = nt & 1;
        int n = (m - 1) * 128 + q * 16 + (gid >> 1) * 4 + p * 2 + (gid & 1);
        v0 = W3[kg * 256 + n];       v1 = W3[(kg + 1) * 256 + n];
        v2 = W3[(kg + 8) * 256 + n]; v3 = W3[(kg + 9) * 256 + n];
        g_w3h[m - 1][(k * 16 + nt) * 32 + lane] =
            make_uint2(pack_f16(__float2half_rn(v0), __float2half_rn(v1)),
                       pack_f16(__float2half_rn(v2), __float2half_rn(v3)));
    }
}

// ---------------- K3: merged per-edge preprocess + output init ----------------
__global__ void k_pre_init(const float* __restrict__ ev,
                           const int* __restrict__ anum, const float* __restrict__ semb,
                           const int* __restrict__ eidx,
                           float* __restrict__ out) {
    if (blockIdx.x >= 938) {
        int idx = (blockIdx.x - 938) * 256 + threadIdx.x;   // over N*128 float4s
        int n = idx >> 7, j4 = idx & 127;
        float4 v = make_float4(0.f, 0.f, 0.f, 0.f);
        if (j4 < 32) v = ((const float4*)semb)[anum[n] * 32 + j4];
        ((float4*)out)[idx] = v;
        return;
    }
    int e = blockIdx.x * 256 + threadIdx.x;
    if (e >= E_NUM) return;

    g_z[e] = (uint32_t)anum[eidx[e]] | ((uint32_t)anum[eidx[E_NUM + e]] << 16);

    float vx = ev[e * 3 + 0], vy = ev[e * 3 + 1], vz = ev[e * 3 + 2];
    float d = sqrtf(vx * vx + vy * vy + vz * vz);
    float dc = fmaxf(d, 1e-8f);
    float nx0 = vx / dc, nx1 = vy / dc, nx2 = vz / dc;

    float a0 = fabsf(nx0), a1 = fabsf(nx1), a2 = fabsf(nx2);
    int idx = 0; float mn = a0;
    if (a1 < mn) { mn = a1; idx = 1; }
    if (a2 < mn) { mn = a2; idx = 2; }
    float r0 = (idx == 0) ? 1.f : 0.f;
    float r1 = (idx == 1) ? 1.f : 0.f;
    float r2 = (idx == 2) ? 1.f : 0.f;

    float nz0 = nx1 * r2 - nx2 * r1;
    float nz1 = nx2 * r0 - nx0 * r2;
    float nz2 = nx0 * r1 - nx1 * r0;
    float nl = fmaxf(sqrtf(nz0 * nz0 + nz1 * nz1 + nz2 * nz2), 1e-8f);
    nz0 /= nl; nz1 /= nl; nz2 /= nl;

    float ny0 = nx1 * nz2 - nx2 * nz1;
    float ny1 = nx2 * nz0 - nx0 * nz2;
    float ny2 = nx0 * nz1 - nx1 * nz0;
    float yl = fmaxf(sqrtf(ny0 * ny0 + ny1 * ny1 + ny2 * ny2), 1e-8f);
    ny0 /= yl; ny1 /= yl; ny2 /= yl;

    g_d1[e] = make_float4(-ny1, -ny2, -ny0, 0.f);

    float u = d * (1.0f / TBL_H) + 4.0f;
    int i; float w0, w1, w2, w3;
    if (u >= (float)(NT - 4)) {
        i = 4; w0 = w1 = w2 = w3 = 0.f;
    } else {
        i = (int)floorf(u);
        float t = u - (float)i;
        w0 = ((-0.5f * t + 1.0f) * t - 0.5f) * t;
        w1 = (1.5f * t - 2.5f) * t * t + 1.0f;
        w2 = ((-1.5f * t + 2.0f) * t + 0.5f) * t;
        w3 = (0.5f * t - 0.5f) * t * t;
    }
    g_i0[e] = i - 1;
    g_w4[e] = make_float4(w0, w1, w2, w3);
}

// ---------------- K4: fused, 8-warp CTA x2/SM; all-fp16 split GEMMs ----------------
__global__ void __launch_bounds__(256, 2)
k_fused(const float* __restrict__ b1, const float* __restrict__ g1v, const float* __restrict__ be1,
        const float* __restrict__ b2v, const float* __restrict__ g2v, const float* __restrict__ be2,
        const float* __restrict__ b3v,
        const int* __restrict__ eidx,
        float* __restrict__ out) {
    extern __shared__ char smem[];
    uint32_t sb = (uint32_t)__cvta_generic_to_shared(smem);
    int tid = threadIdx.x, wid = tid >> 5, lane = tid & 31;
    int e0 = blockIdx.x * 128;
    int m_base = wid * 16;
    int tig = lane & 3, gid = lane >> 2;

    // -------- phase 1: prefetch indices (L2-only), then layer1 for 16 edges --------
    {
        uint32_t zz[16]; int i0s[16];
        #pragma unroll
        for (int i = 0; i < 16; i++) {
            int e = e0 + m_base + i;
            zz[i]  = __ldcg(&g_z[e]);
            i0s[i] = __ldcg(&g_i0[e]);
        }
        int c0 = lane * 4;
        float4 bb  = __ldg((const float4*)b1 + lane);
        float4 gg  = __ldg((const float4*)g1v + lane);
        float4 bv4 = __ldg((const float4*)be1 + lane);
        #pragma unroll 4
        for (int i = 0; i < 16; i++) {
            int r = m_base + i;
            int e = e0 + r;
            int zs = (int)(zz[i] & 0xffffu);
            int zt = (int)(zz[i] >> 16);
            int i0 = i0s[i];
            float4 ww = __ldcg(&g_w4[e]);
            const float4* trow = (const float4*)(g_tbl + (size_t)i0 * C + c0);
            float4 t0 = __ldcg(trow);
            float4 t1 = __ldcg(trow + C / 4);
            float4 t2 = __ldcg(trow + 2 * (C / 4));
            float4 t3 = __ldcg(trow + 3 * (C / 4));
            float4 us = __ldcg((const float4*)(g_embU + zs * C + c0));
            float4 ut = __ldcg((const float4*)(g_embU + (ZMAX + zt) * C + c0));

            float a[4];
            a[0] = bb.x + us.x + ut.x + ww.x * t0.x + ww.y * t1.x + ww.z * t2.x + ww.w * t3.x;
            a[1] = bb.y + us.y + ut.y + ww.x * t0.y + ww.y * t1.y + ww.z * t2.y + ww.w * t3.y;
            a[2] = bb.z + us.z + ut.z + ww.x * t0.z + ww.y * t1.z + ww.z * t2.z + ww.w * t3.z;
            a[3] = bb.w + us.w + ut.w + ww.x * t0.w + ww.y * t1.w + ww.z * t2.w + ww.w * t3.w;

            float s = a[0] + a[1] + a[2] + a[3];
            #pragma unroll
            for (int o = 16; o; o >>= 1) s += __shfl_xor_sync(0xffffffffu, s, o);
            float mu = s * (1.0f / 128.0f);
            float q = 0.f;
            #pragma unroll
            for (int j = 0; j < 4; j++) { float dv = a[j] - mu; q += dv * dv; }
            #pragma unroll
            for (int o = 16; o; o >>= 1) q += __shfl_xor_sync(0xffffffffu, q, o);
            float rstd = rsqrtf(q * (1.0f / 128.0f) + 1e-5f);

            float gv[4] = {gg.x, gg.y, gg.z, gg.w};
            float bv[4] = {bv4.x, bv4.y, bv4.z, bv4.w};
            float o4[4];
            #pragma unroll
            for (int j = 0; j < 4; j++) {
                float y = gv[j] * (a[j] - mu) * rstd + bv[j];
                o4[j] = y / (1.0f + __expf(-y));
            }
            __half h0, h1, h2, h3, l0, l1, l2, l3;
            split_f16(o4[0], h0, l0); split_f16(o4[1], h1, l1);
            split_f16(o4[2], h2, l2); split_f16(o4[3], h3, l3);
            uint32_t boff = swa(r, lane >> 1) + (lane & 1) * 8;
            *(uint2*)(smem + RA_HI + boff) = make_uint2(pack_f16(h0, h1), pack_f16(h2, h3));
            *(uint2*)(smem + RA_LO + boff) = make_uint2(pack_f16(l0, l1), pack_f16(l2, l3));
        }
    }
    __syncwarp();   // warp-local A rows visible to this warp's ldmatrix

    // ldmatrix lane address components
    int lr  = m_base + (lane & 7) + ((lane >> 3) & 1) * 8;
    int lgs = (lane >> 4) & 1;
    int lr7 = lr & 7;
    uint32_t lrb = (uint32_t)(lr * 256);

    // -------- GEMM2: acc = A1 @ W2 (fp16 2-term), B from L1 --------
    float acc[16][4];
    #pragma unroll
    for (int nt = 0; nt < 16; nt++)
        #pragma unroll
        for (int j = 0; j < 4; j++) acc[nt][j] = 0.f;

    #pragma unroll
    for (int k = 0; k < 8; k++) {
        uint32_t aoff = lrb + ((((k * 2 + lgs) ^ lr7)) << 4);
        uint32_t ah0, ah1, ah2, ah3, al0, al1, al2, al3;
        ldsm4(ah0, ah1, ah2, ah3, sb + RA_HI + aoff);
        ldsm4(al0, al1, al2, al3, sb + RA_LO + aoff);
        #pragma unroll
        for (int nt = 0; nt < 16; nt++) {
            uint2 bp = __ldg(g_w2h + (k * 16 + nt) * 32 + lane);
            mma16816h(acc[nt], ah0, ah1, ah2, ah3, bp.x, bp.y);
            mma16816h(acc[nt], al0, al1, al2, al3, bp.x, bp.y);
        }
    }

    // -------- epilogue: +b2, LN, SiLU -> A2 fp16 fragments IN REGISTERS --------
    uint32_t aH[8][4], aL[8][4];
    {
        float sumA = 0.f, sqA = 0.f, sumB = 0.f, sqB = 0.f;
        #pragma unroll
        for (int nt = 0; nt < 16; nt++) {
            int col = nt * 8 + tig * 2;
            float bc0 = __ldg(b2v + col), bc1 = __ldg(b2v + col + 1);
            acc[nt][0] += bc0; acc[nt][1] += bc1;
            acc[nt][2] += bc0; acc[nt][3] += bc1;
            sumA += acc[nt][0] + acc[nt][1];
            sqA  += acc[nt][0] * acc[nt][0] + acc[nt][1] * acc[nt][1];
            sumB += acc[nt][2] + acc[nt][3];
            sqB  += acc[nt][2] * acc[nt][2] + acc[nt][3] * acc[nt][3];
        }
        #pragma unroll
        for (int o = 1; o < 4; o <<= 1) {
            sumA += __shfl_xor_sync(0xffffffffu, sumA, o);
            sqA  += __shfl_xor_sync(0xffffffffu, sqA, o);
            sumB += __shfl_xor_sync(0xffffffffu, sumB, o);
            sqB  += __shfl_xor_sync(0xffffffffu, sqB, o);
        }
        float muA = sumA * (1.0f / 128.0f);
        float muB = sumB * (1.0f / 128.0f);
        float rsA = rsqrtf(fmaxf(sqA * (1.0f / 128.0f) - muA * muA, 0.f) + 1e-5f);
        float rsB = rsqrtf(fmaxf(sqB * (1.0f / 128.0f) - muB * muB, 0.f) + 1e-5f);
        #pragma unroll
        for (int nt = 0; nt < 16; nt++) {
            int col = nt * 8 + tig * 2;
            float gA0 = __ldg(g2v + col), gA1 = __ldg(g2v + col + 1);
            float eA0 = __ldg(be2 + col), eA1 = __ldg(be2 + col + 1);
            float y0 = gA0 * (acc[nt][0] - muA) * rsA + eA0;
            float y1 = gA1 * (acc[nt][1] - muA) * rsA + eA1;
            float y2 = gA0 * (acc[nt][2] - muB) * rsB + eA0;
            float y3 = gA1 * (acc[nt][3] - muB) * rsB + eA1;
            float s0 = y0 / (1.0f + __expf(-y0));
            float s1 = y1 / (1.0f + __expf(-y1));
            float s2 = y2 / (1.0f + __expf(-y2));
            float s3 = y3 / (1.0f + __expf(-y3));
            __half h0, h1, h2, h3, l0, l1, l2, l3;
            split_f16(s0, h0, l0); split_f16(s1, h1, l1);
            split_f16(s2, h2, l2); split_f16(s3, h3, l3);
            int kb = nt >> 1;
            int hi = (nt & 1) << 1;
            aH[kb][hi + 0] = pack_f16(h0, h1);
            aH[kb][hi + 1] = pack_f16(h2, h3);
            aL[kb][hi + 0] = pack_f16(l0, l1);
            aL[kb][hi + 1] = pack_f16(l2, l3);
        }
    }

    // edge metadata for scatter (L2-only loads)
    int rA = m_base + gid, rB = rA + 8;
    int eA = e0 + rA, eB = e0 + rB;
    int dstA = __ldcg(&eidx[E_NUM + eA]);
    int dstB = __ldcg(&eidx[E_NUM + eB]);
    float* baseA = out + (size_t)dstA * 512;
    float* baseB = out + (size_t)dstB * 512;
    float4 ddA = __ldcg(&g_d1[eA]);
    float4 ddB = __ldcg(&g_d1[eB]);
    const float s12 = 1.0f / 12.0f;

    // -------- GEMM3: fp16 2-term, A from registers, B-hi from L1 --------
    #pragma unroll
    for (int half = 0; half < 2; half++) {
        const uint2* wsrc = g_w3h[half];
        #pragma unroll
        for (int q = 0; q < 8; q++) {
            float c0v[4] = {0.f, 0.f, 0.f, 0.f};
            float c1v[4] = {0.f, 0.f, 0.f, 0.f};
            #pragma unroll
            for (int kb = 0; kb < 8; kb++) {
                uint2 bp0 = __ldg(wsrc + (kb * 16 + 2 * q) * 32 + lane);
                uint2 bp1 = __ldg(wsrc + (kb * 16 + 2 * q + 1) * 32 + lane);
                mma16816h(c0v, aH[kb][0], aH[kb][1], aH[kb][2], aH[kb][3], bp0.x, bp0.y);
                mma16816h(c0v, aL[kb][0], aL[kb][1], aL[kb][2], aL[kb][3], bp0.x, bp0.y);
                mma16816h(c1v, aH[kb][0], aH[kb][1], aH[kb][2], aH[kb][3], bp1.x, bp1.y);
                mma16816h(c1v, aL[kb][0], aL[kb][1], aL[kb][2], aL[kb][3], bp1.x, bp1.y);
            }
            // scatter: this thread's 4 values are logical cols q*16+tig*4..+3
            int cb = q * 16 + tig * 4;
            float b0 = __ldg(b3v + half * 128 + cb);
            float b1 = __ldg(b3v + half * 128 + cb + 1);
            float b2_ = __ldg(b3v + half * 128 + cb + 2);
            float b3_ = __ldg(b3v + half * 128 + cb + 3);
            float A0 = (c0v[0] + b0) * s12;
            float A1 = (c0v[1] + b1) * s12;
            float A2 = (c1v[0] + b2_) * s12;
            float A3 = (c1v[1] + b3_) * s12;
            float B0 = (c0v[2] + b0) * s12;
            float B1 = (c0v[3] + b1) * s12;
            float B2 = (c1v[2] + b2_) * s12;
            float B3 = (c1v[3] + b3_) * s12;
            if (half == 0) {
                redv4(baseA + cb, A0, A1, A2, A3);
                redv4(baseB + cb, B0, B1, B2, B3);
            } else {
                redv4(baseA + 128 + cb, A0 * ddA.x, A1 * ddA.x, A2 * ddA.x, A3 * ddA.x);
                redv4(baseA + 256 + cb, A0 * ddA.y, A1 * ddA.y, A2 * ddA.y, A3 * ddA.y);
                redv4(baseA + 384 + cb, A0 * ddA.z, A1 * ddA.z, A2 * ddA.z, A3 * ddA.z);
                redv4(baseB + 128 + cb, B0 * ddB.x, B1 * ddB.x, B2 * ddB.x, B3 * ddB.x);
                redv4(baseB + 256 + cb, B0 * ddB.y, B1 * ddB.y, B2 * ddB.y, B3 * ddB.y);
                redv4(baseB + 384 + cb, B0 * ddB.z, B1 * ddB.z, B2 * ddB.z, B3 * ddB.z);
            }
        }
    }
}

// ---------------- launch ----------------
extern "C" void kernel_launch(void* const* d_in, const int* in_sizes, int n_in,
                              void* d_out, int out_size) {
    const float* ev   = (const float*)d_in[0];
    const float* semb = (const float*)d_in[1];
    const float* srce = (const float*)d_in[2];
    const float* tgte = (const float*)d_in[3];
    const float* W1   = (const float*)d_in[4];
    const float* b1   = (const float*)d_in[5];
    const float* g1_  = (const float*)d_in[6];
    const float* be1  = (const float*)d_in[7];
    const float* W2   = (const float*)d_in[8];
    const float* b2   = (const float*)d_in[9];
    const float* g2_  = (const float*)d_in[10];
    const float* be2  = (const float*)d_in[11];
    const float* W3   = (const float*)d_in[12];
    const float* b3   = (const float*)d_in[13];
    const int*   anum = (const int*)d_in[14];
    const int*   eidx = (const int*)d_in[15];
    float* out = (float*)d_out;

    cudaFuncSetAttribute(k_fused, cudaFuncAttributeMaxDynamicSharedMemorySize, SMEM_BYTES);

    k_table<<<NT, 128>>>(W1);
    k_prep2<<<ZMAX + 48, 256>>>(srce, tgte, W1, W2, W3);
    k_pre_init<<<938 + 10000, 256>>>(ev, anum, semb, eidx, out);
    k_fused<<<E_NUM / 128, 256, SMEM_BYTES>>>(b1, g1_, be1, b2, g2_, be2, b3,
                                              eidx, out);
}

// round 15
// speedup vs baseline: 1.1048x; 1.1048x over previous
#include <cuda_runtime.h>
#include <cuda_bf16.h>
#include <cuda_fp16.h>
#include <math.h>
#include <stdint.h>

#define E_NUM   240000
#define N_NODES 20000
#define C       128
#define NGAUSS  600
#define ZMAX    100
#define NT      5504
#define TBL_H   0.00125f

#define DELTA_OFF 0.0100166944908180f
#define COEFF     (-1245.8368055555557f)

// ---------------- scratch ----------------
__device__ float  g_tbl[NT * C];
__device__ float4 g_w4[E_NUM];
__device__ int    g_i0[E_NUM];
__device__ uint32_t g_z[E_NUM];          // packed (zs | zt<<16)
__device__ float4 g_d1[E_NUM];
__device__ float  g_embU[2 * ZMAX * C];
__device__ uint2  g_w2h[4096];           // W2 fp16 per (k*16+nt)*32+lane (32KB)
__device__ uint2  g_w3h[2][4096];        // W3 fp16, [half], n-permuted (64KB)

// smem: A1 fp16 32KB (128 rows x 256B). Weights live in L1.
#define RA_HI 0
#define SMEM_BYTES 32768

// swizzled row-major 16-bit tile offset: row r (0..127), 16B granule g (0..15)
__device__ __forceinline__ uint32_t swa(int r, int g) {
    return (uint32_t)(r * 256 + (((g) ^ (r & 7)) << 4));
}

// ---------------- PTX helpers ----------------
__device__ __forceinline__ void redv4(float* p, float a, float b, float c, float d) {
    asm volatile("red.global.add.v4.f32 [%0], {%1,%2,%3,%4};"
                 :: "l"(p), "f"(a), "f"(b), "f"(c), "f"(d) : "memory");
}
__device__ __forceinline__ void ldsm4(uint32_t& r0, uint32_t& r1, uint32_t& r2, uint32_t& r3,
                                      uint32_t addr) {
    asm volatile("ldmatrix.sync.aligned.m8n8.x4.shared.b16 {%0,%1,%2,%3}, [%4];"
                 : "=r"(r0), "=r"(r1), "=r"(r2), "=r"(r3) : "r"(addr));
}
__device__ __forceinline__ void mma16816h(float* c, uint32_t a0, uint32_t a1, uint32_t a2,
                                          uint32_t a3, uint32_t b0, uint32_t b1) {
    asm volatile("mma.sync.aligned.m16n8k16.row.col.f32.f16.f16.f32 "
                 "{%0,%1,%2,%3}, {%4,%5,%6,%7}, {%8,%9}, {%0,%1,%2,%3};"
                 : "+f"(c[0]), "+f"(c[1]), "+f"(c[2]), "+f"(c[3])
                 : "r"(a0), "r"(a1), "r"(a2), "r"(a3), "r"(b0), "r"(b1));
}
__device__ __forceinline__ uint32_t pack_f16(__half lo, __half hi) {
    return (uint32_t)__half_as_ushort(lo) | ((uint32_t)__half_as_ushort(hi) << 16);
}

// ---------------- K1: F table ----------------
__global__ void k_table(const float* __restrict__ W1) {
    int row = blockIdx.x;
    int c   = threadIdx.x;
    float x = (row - 4) * TBL_H;
    int gc = (int)rintf(x / DELTA_OFF);
    int g0 = max(gc - 24, 0);
    int g1 = min(gc + 24, NGAUSS - 1);
    __shared__ float sw[64];
    int nw = g1 - g0 + 1;
    if (c < nw) {
        float o = (g0 + c) * DELTA_OFF;
        float dd = x - o;
        sw[c] = __expf(COEFF * dd * dd);
    }
    __syncthreads();
    float acc = 0.f;
    for (int j = 0; j < nw; j++)
        acc += sw[j] * W1[(g0 + j) * C + c];
    g_tbl[row * C + c] = acc;
}

// ---------------- K2: merged embW-fold + weight prepack ----------------
__global__ void k_prep2(const float* __restrict__ srce, const float* __restrict__ tgte,
                        const float* __restrict__ W1,
                        const float* __restrict__ W2, const float* __restrict__ W3) {
    if (blockIdx.x < ZMAX) {
        int z = blockIdx.x;
        int w = threadIdx.x >> 7;
        int c = threadIdx.x & 127;
        const float* emb = w ? tgte : srce;
        const float* Wb  = W1 + (NGAUSS + w * C) * C;
        __shared__ float se[2][C];
        se[w][c] = emb[z * C + c];
        __syncthreads();
        float acc = 0.f;
        #pragma unroll 8
        for (int k = 0; k < C; k++)
            acc = fmaf(se[w][k], Wb[k * C + c], acc);
        g_embU[(w * ZMAX + z) * C + c] = acc;
        return;
    }
    int idx = (blockIdx.x - ZMAX) * 256 + threadIdx.x;
    if (idx >= 12288) return;
    int lane = idx & 31;
    int nt   = (idx >> 5) & 15;
    int k    = (idx >> 9) & 7;
    int m    = idx >> 12;            // 0: W2, 1: W3 half0, 2: W3 half1
    int tig = lane & 3, gid = lane >> 2;
    int kg = k * 16 + tig * 2;
    float v0, v1, v2, v3;
    if (m == 0) {
        int n = nt * 8 + gid;
        v0 = W2[kg * C + n];       v1 = W2[(kg + 1) * C + n];
        v2 = W2[(kg + 8) * C + n]; v3 = W2[(kg + 9) * C + n];
        g_w2h[(k * 16 + nt) * 32 + lane] =
            make_uint2(pack_f16(__float2half_rn(v0), __float2half_rn(v1)),
                       pack_f16(__float2half_rn(v2), __float2half_rn(v3)));
    } else {
        // permuted: logical col L(nt=2q+p, j=gid) = q*16 + (j>>1)*4 + p*2 + (j&1)
        int q = nt >> 1, p = nt & 1;
        int n = (m - 1) * 128 + q * 16 + (gid >> 1) * 4 + p * 2 + (gid & 1);
        v0 = W3[kg * 256 + n];       v1 = W3[(kg + 1) * 256 + n];
        v2 = W3[(kg + 8) * 256 + n]; v3 = W3[(kg + 9) * 256 + n];
        g_w3h[m - 1][(k * 16 + nt) * 32 + lane] =
            make_uint2(pack_f16(__float2half_rn(v0), __float2half_rn(v1)),
                       pack_f16(__float2half_rn(v2), __float2half_rn(v3)));
    }
}

// ---------------- K3: merged per-edge preprocess + output init ----------------
__global__ void k_pre_init(const float* __restrict__ ev,
                           const int* __restrict__ anum, const float* __restrict__ semb,
                           const int* __restrict__ eidx,
                           float* __restrict__ out) {
    if (blockIdx.x >= 938) {
        int idx = (blockIdx.x - 938) * 256 + threadIdx.x;   // over N*128 float4s
        int n = idx >> 7, j4 = idx & 127;
        float4 v = make_float4(0.f, 0.f, 0.f, 0.f);
        if (j4 < 32) v = ((const float4*)semb)[anum[n] * 32 + j4];
        ((float4*)out)[idx] = v;
        return;
    }
    int e = blockIdx.x * 256 + threadIdx.x;
    if (e >= E_NUM) return;

    g_z[e] = (uint32_t)anum[eidx[e]] | ((uint32_t)anum[eidx[E_NUM + e]] << 16);

    float vx = ev[e * 3 + 0], vy = ev[e * 3 + 1], vz = ev[e * 3 + 2];
    float d = sqrtf(vx * vx + vy * vy + vz * vz);
    float dc = fmaxf(d, 1e-8f);
    float nx0 = vx / dc, nx1 = vy / dc, nx2 = vz / dc;

    float a0 = fabsf(nx0), a1 = fabsf(nx1), a2 = fabsf(nx2);
    int idx = 0; float mn = a0;
    if (a1 < mn) { mn = a1; idx = 1; }
    if (a2 < mn) { mn = a2; idx = 2; }
    float r0 = (idx == 0) ? 1.f : 0.f;
    float r1 = (idx == 1) ? 1.f : 0.f;
    float r2 = (idx == 2) ? 1.f : 0.f;

    float nz0 = nx1 * r2 - nx2 * r1;
    float nz1 = nx2 * r0 - nx0 * r2;
    float nz2 = nx0 * r1 - nx1 * r0;
    float nl = fmaxf(sqrtf(nz0 * nz0 + nz1 * nz1 + nz2 * nz2), 1e-8f);
    nz0 /= nl; nz1 /= nl; nz2 /= nl;

    float ny0 = nx1 * nz2 - nx2 * nz1;
    float ny1 = nx2 * nz0 - nx0 * nz2;
    float ny2 = nx0 * nz1 - nx1 * nz0;
    float yl = fmaxf(sqrtf(ny0 * ny0 + ny1 * ny1 + ny2 * ny2), 1e-8f);
    ny0 /= yl; ny1 /= yl; ny2 /= yl;

    g_d1[e] = make_float4(-ny1, -ny2, -ny0, 0.f);

    float u = d * (1.0f / TBL_H) + 4.0f;
    int i; float w0, w1, w2, w3;
    if (u >= (float)(NT - 4)) {
        i = 4; w0 = w1 = w2 = w3 = 0.f;
    } else {
        i = (int)floorf(u);
        float t = u - (float)i;
        w0 = ((-0.5f * t + 1.0f) * t - 0.5f) * t;
        w1 = (1.5f * t - 2.5f) * t * t + 1.0f;
        w2 = ((-1.5f * t + 2.0f) * t + 0.5f) * t;
        w3 = (0.5f * t - 0.5f) * t * t;
    }
    g_i0[e] = i - 1;
    g_w4[e] = make_float4(w0, w1, w2, w3);
}

// ---------------- K4: fused, 8-warp CTA x2/SM; single-term fp16 GEMMs ----------------
__global__ void __launch_bounds__(256, 2)
k_fused(const float* __restrict__ b1, const float* __restrict__ g1v, const float* __restrict__ be1,
        const float* __restrict__ b2v, const float* __restrict__ g2v, const float* __restrict__ be2,
        const float* __restrict__ b3v,
        const int* __restrict__ eidx,
        float* __restrict__ out) {
    extern __shared__ char smem[];
    uint32_t sb = (uint32_t)__cvta_generic_to_shared(smem);
    int tid = threadIdx.x, wid = tid >> 5, lane = tid & 31;
    int e0 = blockIdx.x * 128;
    int m_base = wid * 16;
    int tig = lane & 3, gid = lane >> 2;

    // -------- phase 1: prefetch indices (L2-only), then layer1 for 16 edges --------
    {
        uint32_t zz[16]; int i0s[16];
        #pragma unroll
        for (int i = 0; i < 16; i++) {
            int e = e0 + m_base + i;
            zz[i]  = __ldcg(&g_z[e]);
            i0s[i] = __ldcg(&g_i0[e]);
        }
        int c0 = lane * 4;
        float4 bb  = __ldg((const float4*)b1 + lane);
        float4 gg  = __ldg((const float4*)g1v + lane);
        float4 bv4 = __ldg((const float4*)be1 + lane);
        #pragma unroll 4
        for (int i = 0; i < 16; i++) {
            int r = m_base + i;
            int e = e0 + r;
            int zs = (int)(zz[i] & 0xffffu);
            int zt = (int)(zz[i] >> 16);
            int i0 = i0s[i];
            float4 ww = __ldcg(&g_w4[e]);
            const float4* trow = (const float4*)(g_tbl + (size_t)i0 * C + c0);
            float4 t0 = __ldcg(trow);
            float4 t1 = __ldcg(trow + C / 4);
            float4 t2 = __ldcg(trow + 2 * (C / 4));
            float4 t3 = __ldcg(trow + 3 * (C / 4));
            float4 us = __ldcg((const float4*)(g_embU + zs * C + c0));
            float4 ut = __ldcg((const float4*)(g_embU + (ZMAX + zt) * C + c0));

            float a[4];
            a[0] = bb.x + us.x + ut.x + ww.x * t0.x + ww.y * t1.x + ww.z * t2.x + ww.w * t3.x;
            a[1] = bb.y + us.y + ut.y + ww.x * t0.y + ww.y * t1.y + ww.z * t2.y + ww.w * t3.y;
            a[2] = bb.z + us.z + ut.z + ww.x * t0.z + ww.y * t1.z + ww.z * t2.z + ww.w * t3.z;
            a[3] = bb.w + us.w + ut.w + ww.x * t0.w + ww.y * t1.w + ww.z * t2.w + ww.w * t3.w;

            float s = a[0] + a[1] + a[2] + a[3];
            #pragma unroll
            for (int o = 16; o; o >>= 1) s += __shfl_xor_sync(0xffffffffu, s, o);
            float mu = s * (1.0f / 128.0f);
            float q = 0.f;
            #pragma unroll
            for (int j = 0; j < 4; j++) { float dv = a[j] - mu; q += dv * dv; }
            #pragma unroll
            for (int o = 16; o; o >>= 1) q += __shfl_xor_sync(0xffffffffu, q, o);
            float rstd = rsqrtf(q * (1.0f / 128.0f) + 1e-5f);

            float gv[4] = {gg.x, gg.y, gg.z, gg.w};
            float bv[4] = {bv4.x, bv4.y, bv4.z, bv4.w};
            float o4[4];
            #pragma unroll
            for (int j = 0; j < 4; j++) {
                float y = gv[j] * (a[j] - mu) * rstd + bv[j];
                o4[j] = y / (1.0f + __expf(-y));
            }
            uint32_t boff = swa(r, lane >> 1) + (lane & 1) * 8;
            *(uint2*)(smem + RA_HI + boff) =
                make_uint2(pack_f16(__float2half_rn(o4[0]), __float2half_rn(o4[1])),
                           pack_f16(__float2half_rn(o4[2]), __float2half_rn(o4[3])));
        }
    }
    __syncwarp();   // warp-local A rows visible to this warp's ldmatrix

    // ldmatrix lane address components
    int lr  = m_base + (lane & 7) + ((lane >> 3) & 1) * 8;
    int lgs = (lane >> 4) & 1;
    int lr7 = lr & 7;
    uint32_t lrb = (uint32_t)(lr * 256);

    // -------- GEMM2: acc = A1 @ W2 (single fp16), B from L1 --------
    float acc[16][4];
    #pragma unroll
    for (int nt = 0; nt < 16; nt++)
        #pragma unroll
        for (int j = 0; j < 4; j++) acc[nt][j] = 0.f;

    #pragma unroll
    for (int k = 0; k < 8; k++) {
        uint32_t aoff = lrb + ((((k * 2 + lgs) ^ lr7)) << 4);
        uint32_t ah0, ah1, ah2, ah3;
        ldsm4(ah0, ah1, ah2, ah3, sb + RA_HI + aoff);
        #pragma unroll
        for (int nt = 0; nt < 16; nt++) {
            uint2 bp = __ldg(g_w2h + (k * 16 + nt) * 32 + lane);
            mma16816h(acc[nt], ah0, ah1, ah2, ah3, bp.x, bp.y);
        }
    }

    // -------- epilogue: +b2, LN, SiLU -> A2 fp16 fragments IN REGISTERS --------
    uint32_t aH[8][4];
    {
        float sumA = 0.f, sqA = 0.f, sumB = 0.f, sqB = 0.f;
        #pragma unroll
        for (int nt = 0; nt < 16; nt++) {
            int col = nt * 8 + tig * 2;
            float bc0 = __ldg(b2v + col), bc1 = __ldg(b2v + col + 1);
            acc[nt][0] += bc0; acc[nt][1] += bc1;
            acc[nt][2] += bc0; acc[nt][3] += bc1;
            sumA += acc[nt][0] + acc[nt][1];
            sqA  += acc[nt][0] * acc[nt][0] + acc[nt][1] * acc[nt][1];
            sumB += acc[nt][2] + acc[nt][3];
            sqB  += acc[nt][2] * acc[nt][2] + acc[nt][3] * acc[nt][3];
        }
        #pragma unroll
        for (int o = 1; o < 4; o <<= 1) {
            sumA += __shfl_xor_sync(0xffffffffu, sumA, o);
            sqA  += __shfl_xor_sync(0xffffffffu, sqA, o);
            sumB += __shfl_xor_sync(0xffffffffu, sumB, o);
            sqB  += __shfl_xor_sync(0xffffffffu, sqB, o);
        }
        float muA = sumA * (1.0f / 128.0f);
        float muB = sumB * (1.0f / 128.0f);
        float rsA = rsqrtf(fmaxf(sqA * (1.0f / 128.0f) - muA * muA, 0.f) + 1e-5f);
        float rsB = rsqrtf(fmaxf(sqB * (1.0f / 128.0f) - muB * muB, 0.f) + 1e-5f);
        #pragma unroll
        for (int nt = 0; nt < 16; nt++) {
            int col = nt * 8 + tig * 2;
            float gA0 = __ldg(g2v + col), gA1 = __ldg(g2v + col + 1);
            float eA0 = __ldg(be2 + col), eA1 = __ldg(be2 + col + 1);
            float y0 = gA0 * (acc[nt][0] - muA) * rsA + eA0;
            float y1 = gA1 * (acc[nt][1] - muA) * rsA + eA1;
            float y2 = gA0 * (acc[nt][2] - muB) * rsB + eA0;
            float y3 = gA1 * (acc[nt][3] - muB) * rsB + eA1;
            float s0 = y0 / (1.0f + __expf(-y0));
            float s1 = y1 / (1.0f + __expf(-y1));
            float s2 = y2 / (1.0f + __expf(-y2));
            float s3 = y3 / (1.0f + __expf(-y3));
            int kb = nt >> 1;
            int hi = (nt & 1) << 1;
            aH[kb][hi + 0] = pack_f16(__float2half_rn(s0), __float2half_rn(s1));
            aH[kb][hi + 1] = pack_f16(__float2half_rn(s2), __float2half_rn(s3));
        }
    }

    // edge metadata for scatter (L2-only loads)
    int rA = m_base + gid, rB = rA + 8;
    int eA = e0 + rA, eB = e0 + rB;
    int dstA = __ldcg(&eidx[E_NUM + eA]);
    int dstB = __ldcg(&eidx[E_NUM + eB]);
    float* baseA = out + (size_t)dstA * 512;
    float* baseB = out + (size_t)dstB * 512;
    float4 ddA = __ldcg(&g_d1[eA]);
    float4 ddB = __ldcg(&g_d1[eB]);
    const float s12 = 1.0f / 12.0f;

    // -------- GEMM3: single fp16, A from registers, B from L1 --------
    #pragma unroll
    for (int half = 0; half < 2; half++) {
        const uint2* wsrc = g_w3h[half];
        #pragma unroll
        for (int q = 0; q < 8; q++) {
            float c0v[4] = {0.f, 0.f, 0.f, 0.f};
            float c1v[4] = {0.f, 0.f, 0.f, 0.f};
            #pragma unroll
            for (int kb = 0; kb < 8; kb++) {
                uint2 bp0 = __ldg(wsrc + (kb * 16 + 2 * q) * 32 + lane);
                uint2 bp1 = __ldg(wsrc + (kb * 16 + 2 * q + 1) * 32 + lane);
                mma16816h(c0v, aH[kb][0], aH[kb][1], aH[kb][2], aH[kb][3], bp0.x, bp0.y);
                mma16816h(c1v, aH[kb][0], aH[kb][1], aH[kb][2], aH[kb][3], bp1.x, bp1.y);
            }
            // scatter: this thread's 4 values are logical cols q*16+tig*4..+3
            int cb = q * 16 + tig * 4;
            float b0 = __ldg(b3v + half * 128 + cb);
            float b1 = __ldg(b3v + half * 128 + cb + 1);
            float b2_ = __ldg(b3v + half * 128 + cb + 2);
            float b3_ = __ldg(b3v + half * 128 + cb + 3);
            float A0 = (c0v[0] + b0) * s12;
            float A1 = (c0v[1] + b1) * s12;
            float A2 = (c1v[0] + b2_) * s12;
            float A3 = (c1v[1] + b3_) * s12;
            float B0 = (c0v[2] + b0) * s12;
            float B1 = (c0v[3] + b1) * s12;
            float B2 = (c1v[2] + b2_) * s12;
            float B3 = (c1v[3] + b3_) * s12;
            if (half == 0) {
                redv4(baseA + cb, A0, A1, A2, A3);
                redv4(baseB + cb, B0, B1, B2, B3);
            } else {
                redv4(baseA + 128 + cb, A0 * ddA.x, A1 * ddA.x, A2 * ddA.x, A3 * ddA.x);
                redv4(baseA + 256 + cb, A0 * ddA.y, A1 * ddA.y, A2 * ddA.y, A3 * ddA.y);
                redv4(baseA + 384 + cb, A0 * ddA.z, A1 * ddA.z, A2 * ddA.z, A3 * ddA.z);
                redv4(baseB + 128 + cb, B0 * ddB.x, B1 * ddB.x, B2 * ddB.x, B3 * ddB.x);
                redv4(baseB + 256 + cb, B0 * ddB.y, B1 * ddB.y, B2 * ddB.y, B3 * ddB.y);
                redv4(baseB + 384 + cb, B0 * ddB.z, B1 * ddB.z, B2 * ddB.z, B3 * ddB.z);
            }
        }
    }
}

// ---------------- launch ----------------
extern "C" void kernel_launch(void* const* d_in, const int* in_sizes, int n_in,
                              void* d_out, int out_size) {
    const float* ev   = (const float*)d_in[0];
    const float* semb = (const float*)d_in[1];
    const float* srce = (const float*)d_in[2];
    const float* tgte = (const float*)d_in[3];
    const float* W1   = (const float*)d_in[4];
    const float* b1   = (const float*)d_in[5];
    const float* g1_  = (const float*)d_in[6];
    const float* be1  = (const float*)d_in[7];
    const float* W2   = (const float*)d_in[8];
    const float* b2   = (const float*)d_in[9];
    const float* g2_  = (const float*)d_in[10];
    const float* be2  = (const float*)d_in[11];
    const float* W3   = (const float*)d_in[12];
    const float* b3   = (const float*)d_in[13];
    const int*   anum = (const int*)d_in[14];
    const int*   eidx = (const int*)d_in[15];
    float* out = (float*)d_out;

    cudaFuncSetAttribute(k_fused, cudaFuncAttributeMaxDynamicSharedMemorySize, SMEM_BYTES);

    k_table<<<NT, 128>>>(W1);
    k_prep2<<<ZMAX + 48, 256>>>(srce, tgte, W1, W2, W3);
    k_pre_init<<<938 + 10000, 256>>>(ev, anum, semb, eidx, out);
    k_fused<<<E_NUM / 128, 256, SMEM_BYTES>>>(b1, g1_, be1, b2, g2_, be2, b3,
                                              eidx, out);
}